// round 1
// baseline (speedup 1.0000x reference)
#include <cuda_runtime.h>
#include <stdint.h>

#define BB 8
#define NN 8192
#define CC 64
#define NPOINT 2048
#define NSAMPLE 32
#define RADIUS2 0.04f
#define P_TOTAL (BB*NPOINT*NSAMPLE)   // 524288

// ---------------- scratch (device globals; no allocation allowed) ------------
__device__ float d_featT[BB*NN*CC];                 // 16.8 MB  (B,N,C)
__device__ int   d_fps_idx[BB*NPOINT];
__device__ int   d_ball_idx[P_TOTAL];
__device__ float d_h1[(size_t)64*P_TOTAL];          // 134 MB
__device__ float d_h2[(size_t)64*P_TOTAL];          // 134 MB
__device__ float d_h3[(size_t)128*P_TOTAL];         // 268 MB
__device__ float d_partials[4096*128*2];            // 4 MB
__device__ float d_ab[128*2];                       // fused BN scale/shift

// ---------------- feature transpose (B,C,N) -> (B,N,C) -----------------------
__global__ void k_transpose(const float* __restrict__ f) {
    __shared__ float tile[32][33];
    int b = blockIdx.z, n0 = blockIdx.x*32, c0 = blockIdx.y*32;
    int tx = threadIdx.x, ty = threadIdx.y;
    for (int i = ty; i < 32; i += 8)
        tile[i][tx] = f[((size_t)b*CC + c0 + i)*NN + n0 + tx];
    __syncthreads();
    for (int i = ty; i < 32; i += 8)
        d_featT[((size_t)b*NN + n0 + i)*CC + c0 + tx] = tile[tx][i];
}

// ---------------- furthest point sampling ------------------------------------
// One CTA per batch. 512 threads, 16 points each, everything register-resident.
__global__ __launch_bounds__(512,1) void k_fps(const float* __restrict__ xyz,
                                               float* __restrict__ out_newxyz) {
    const int b = blockIdx.x;
    const int tid = threadIdx.x;
    const float* xb = xyz + (size_t)b*NN*3;

    float px[16], py[16], pz[16], dd[16];
#pragma unroll
    for (int k = 0; k < 16; k++) {
        int pt = k*512 + tid;
        px[k] = xb[pt*3+0]; py[k] = xb[pt*3+1]; pz[k] = xb[pt*3+2];
        dd[k] = 1e10f;
    }
    __shared__ float s_last[3];
    __shared__ unsigned s_val[16];
    __shared__ int s_idx[16];

    if (tid == 0) {
        d_fps_idx[b*NPOINT] = 0;
        float x0 = xb[0], y0 = xb[1], z0 = xb[2];
        s_last[0] = x0; s_last[1] = y0; s_last[2] = z0;
        float* o = out_newxyz + (size_t)b*NPOINT*3;
        o[0] = x0; o[1] = y0; o[2] = z0;
    }
    __syncthreads();

    for (int it = 1; it < NPOINT; it++) {
        float lx = s_last[0], ly = s_last[1], lz = s_last[2];
        float bestv = -1.0f; int besti = 0x7fffffff;
#pragma unroll
        for (int k = 0; k < 16; k++) {
            // match XLA: no FMA contraction, left-to-right sum
            float dx = px[k]-lx, dy = py[k]-ly, dz = pz[k]-lz;
            float d = __fadd_rn(__fadd_rn(__fmul_rn(dx,dx), __fmul_rn(dy,dy)),
                                __fmul_rn(dz,dz));
            float nd = fminf(dd[k], d);
            dd[k] = nd;
            if (nd > bestv) { bestv = nd; besti = k*512 + tid; }
        }
        unsigned vb   = __float_as_uint(bestv);           // bestv >= 0: monotone bits
        unsigned wmax = __reduce_max_sync(0xffffffffu, vb);
        int cand = (vb == wmax) ? besti : 0x7fffffff;
        int wmin = __reduce_min_sync(0xffffffffu, cand);  // first-index tie-break
        if ((tid & 31) == 0) { s_val[tid>>5] = wmax; s_idx[tid>>5] = wmin; }
        __syncthreads();
        if (tid < 32) {
            unsigned v = (tid < 16) ? s_val[tid] : 0u;
            int      i = (tid < 16) ? s_idx[tid] : 0x7fffffff;
            unsigned m2 = __reduce_max_sync(0xffffffffu, v);
            int c2 = (v == m2) ? i : 0x7fffffff;
            int gi = __reduce_min_sync(0xffffffffu, c2);
            if (tid == 0) {
                d_fps_idx[b*NPOINT + it] = gi;
                float gx = xb[gi*3+0], gy = xb[gi*3+1], gz = xb[gi*3+2];
                s_last[0] = gx; s_last[1] = gy; s_last[2] = gz;
                float* o = out_newxyz + ((size_t)b*NPOINT + it)*3;
                o[0] = gx; o[1] = gy; o[2] = gz;
            }
        }
        __syncthreads();
    }
}

// ---------------- ball query: warp per (b,s), first-32 in index order --------
__global__ void k_ballquery(const float* __restrict__ xyz,
                            const float* __restrict__ newxyz) {
    int warp = (blockIdx.x*blockDim.x + threadIdx.x) >> 5;
    int lane = threadIdx.x & 31;
    if (warp >= BB*NPOINT) return;
    int b = warp / NPOINT;
    const float* xb = xyz + (size_t)b*NN*3;
    const float* np = newxyz + (size_t)warp*3;
    float qx = np[0], qy = np[1], qz = np[2];
    int* outp = d_ball_idx + (size_t)warp*NSAMPLE;

    int cnt = 0, firstIdx = 0; bool haveFirst = false;
    for (int j0 = 0; j0 < NN && cnt < NSAMPLE; j0 += 32) {
        int j = j0 + lane;
        float dx = __fadd_rn(xb[j*3+0], -qx);
        float dy = __fadd_rn(xb[j*3+1], -qy);
        float dz = __fadd_rn(xb[j*3+2], -qz);
        float d = __fadd_rn(__fadd_rn(__fmul_rn(dx,dx), __fmul_rn(dy,dy)),
                            __fmul_rn(dz,dz));
        bool in = d < RADIUS2;
        unsigned m = __ballot_sync(0xffffffffu, in);
        if (m) {
            if (!haveFirst) { firstIdx = j0 + __ffs(m) - 1; haveFirst = true; }
            if (in) {
                int pos = cnt + __popc(m & ((1u << lane) - 1u));
                if (pos < NSAMPLE) outp[pos] = j;
            }
            cnt += __popc(m);
        }
    }
    int fs = cnt < NSAMPLE ? cnt : NSAMPLE;
    for (int pos = fs + lane; pos < NSAMPLE; pos += 32) outp[pos] = firstIdx;
}

// ---------------- layer 1: gather + GEMM(64x67) + stat partials --------------
// tile: 64 out x 256 pos, 256 threads, each 8x8
__global__ __launch_bounds__(256,2) void k_layer1(const float* __restrict__ xyz,
                                                  const float* __restrict__ newxyz,
                                                  const float* __restrict__ W1) {
    extern __shared__ float sm[];
    float (*sg)[256] = (float(*)[256])sm;              // 67 x 256
    float (*sw)[64]  = (float(*)[64])(sm + 67*256);    // 67 x 64
    int tid = threadIdx.x;
    int pos0 = blockIdx.x * 256;

    for (int i = tid; i < 64*67; i += 256) { int o = i/67, c = i%67; sw[c][o] = W1[i]; }
    {   // gather one position per thread
        int pos = pos0 + tid;
        int idx = d_ball_idx[pos];
        int b = pos >> 16;              // /(2048*32)
        int s = (pos >> 5) & 2047;
        const float* nx = newxyz + ((size_t)b*NPOINT + s)*3;
        const float* pp = xyz + ((size_t)b*NN + idx)*3;
        sg[0][tid] = pp[0]-nx[0];
        sg[1][tid] = pp[1]-nx[1];
        sg[2][tid] = pp[2]-nx[2];
        const float4* fr = (const float4*)(d_featT + ((size_t)b*NN + idx)*CC);
#pragma unroll
        for (int c4 = 0; c4 < 16; c4++) {
            float4 v = fr[c4];
            sg[3+c4*4+0][tid] = v.x; sg[3+c4*4+1][tid] = v.y;
            sg[3+c4*4+2][tid] = v.z; sg[3+c4*4+3][tid] = v.w;
        }
    }
    __syncthreads();

    int tr = tid >> 5, tc = tid & 31;
    float acc[8][8];
#pragma unroll
    for (int i=0;i<8;i++)
#pragma unroll
        for (int j=0;j<8;j++) acc[i][j]=0.f;

#pragma unroll 2
    for (int k = 0; k < 67; k++) {
        float w[8], g[8];
        *(float4*)&w[0] = *(const float4*)&sw[k][tr*8];
        *(float4*)&w[4] = *(const float4*)&sw[k][tr*8+4];
        *(float4*)&g[0] = *(const float4*)&sg[k][tc*8];
        *(float4*)&g[4] = *(const float4*)&sg[k][tc*8+4];
#pragma unroll
        for (int i=0;i<8;i++)
#pragma unroll
            for (int j=0;j<8;j++) acc[i][j] += w[i]*g[j];
    }
#pragma unroll
    for (int i = 0; i < 8; i++) {
        int c = tr*8 + i;
        float* hp = d_h1 + (size_t)c*P_TOTAL + pos0 + tc*8;
        *(float4*)hp     = make_float4(acc[i][0],acc[i][1],acc[i][2],acc[i][3]);
        *(float4*)(hp+4) = make_float4(acc[i][4],acc[i][5],acc[i][6],acc[i][7]);
    }
#pragma unroll
    for (int i = 0; i < 8; i++) {
        float s = 0.f, q = 0.f;
#pragma unroll
        for (int j = 0; j < 8; j++) { s += acc[i][j]; q += acc[i][j]*acc[i][j]; }
#pragma unroll
        for (int o = 16; o > 0; o >>= 1) {
            s += __shfl_xor_sync(0xffffffffu, s, o);
            q += __shfl_xor_sync(0xffffffffu, q, o);
        }
        if (tc == 0) {
            int c = tr*8 + i;
            d_partials[((size_t)blockIdx.x*128 + c)*2 + 0] = s;
            d_partials[((size_t)blockIdx.x*128 + c)*2 + 1] = q;
        }
    }
}

// ---------------- deterministic stats reduce + BN fold -----------------------
__global__ void k_stats(const float* __restrict__ gam, const float* __restrict__ bet,
                        int nblocks) {
    int c = blockIdx.x, t = threadIdx.x;
    double s = 0.0, q = 0.0;
    for (int i = t; i < nblocks; i += 256) {
        s += (double)d_partials[((size_t)i*128 + c)*2 + 0];
        q += (double)d_partials[((size_t)i*128 + c)*2 + 1];
    }
    __shared__ double ss[256], qq[256];
    ss[t] = s; qq[t] = q; __syncthreads();
    for (int o = 128; o > 0; o >>= 1) {
        if (t < o) { ss[t] += ss[t+o]; qq[t] += qq[t+o]; }
        __syncthreads();
    }
    if (t == 0) {
        double mu  = ss[0] / (double)P_TOTAL;
        double var = qq[0] / (double)P_TOTAL - mu*mu;
        float a  = (float)((double)gam[c] / sqrt(var + 1e-5));
        float bp = (float)((double)bet[c] - mu * (double)a);
        d_ab[c*2] = a; d_ab[c*2+1] = bp;
    }
}

// ---------------- layer 2: bn1+relu on load, GEMM(64x64) ---------------------
__global__ __launch_bounds__(256,2) void k_layer2(const float* __restrict__ W2) {
    extern __shared__ float sm[];
    float (*sg)[256] = (float(*)[256])sm;              // 64 x 256
    float (*sw)[64]  = (float(*)[64])(sm + 64*256);    // 64 x 64
    int tid = threadIdx.x;
    int pos0 = blockIdx.x * 256;
    int wid = tid >> 5, lane = tid & 31;

    for (int i = tid; i < 64*64; i += 256) { int o = i/64, c = i%64; sw[c][o] = W2[i]; }
    for (int c = wid; c < 64; c += 8) {
        float a = d_ab[c*2], bp = d_ab[c*2+1];
        const float4* src = (const float4*)(d_h1 + (size_t)c*P_TOTAL + pos0) + lane*2;
        float4 v0 = src[0], v1 = src[1];
        v0.x=fmaxf(0.f,a*v0.x+bp); v0.y=fmaxf(0.f,a*v0.y+bp);
        v0.z=fmaxf(0.f,a*v0.z+bp); v0.w=fmaxf(0.f,a*v0.w+bp);
        v1.x=fmaxf(0.f,a*v1.x+bp); v1.y=fmaxf(0.f,a*v1.y+bp);
        v1.z=fmaxf(0.f,a*v1.z+bp); v1.w=fmaxf(0.f,a*v1.w+bp);
        *(float4*)&sg[c][lane*8]   = v0;
        *(float4*)&sg[c][lane*8+4] = v1;
    }
    __syncthreads();

    int tr = wid, tc = lane;
    float acc[8][8];
#pragma unroll
    for (int i=0;i<8;i++)
#pragma unroll
        for (int j=0;j<8;j++) acc[i][j]=0.f;
#pragma unroll 2
    for (int k = 0; k < 64; k++) {
        float w[8], g[8];
        *(float4*)&w[0] = *(const float4*)&sw[k][tr*8];
        *(float4*)&w[4] = *(const float4*)&sw[k][tr*8+4];
        *(float4*)&g[0] = *(const float4*)&sg[k][tc*8];
        *(float4*)&g[4] = *(const float4*)&sg[k][tc*8+4];
#pragma unroll
        for (int i=0;i<8;i++)
#pragma unroll
            for (int j=0;j<8;j++) acc[i][j] += w[i]*g[j];
    }
#pragma unroll
    for (int i = 0; i < 8; i++) {
        int c = tr*8 + i;
        float* hp = d_h2 + (size_t)c*P_TOTAL + pos0 + tc*8;
        *(float4*)hp     = make_float4(acc[i][0],acc[i][1],acc[i][2],acc[i][3]);
        *(float4*)(hp+4) = make_float4(acc[i][4],acc[i][5],acc[i][6],acc[i][7]);
    }
#pragma unroll
    for (int i = 0; i < 8; i++) {
        float s = 0.f, q = 0.f;
#pragma unroll
        for (int j = 0; j < 8; j++) { s += acc[i][j]; q += acc[i][j]*acc[i][j]; }
#pragma unroll
        for (int o = 16; o > 0; o >>= 1) {
            s += __shfl_xor_sync(0xffffffffu, s, o);
            q += __shfl_xor_sync(0xffffffffu, q, o);
        }
        if (tc == 0) {
            int c = tr*8 + i;
            d_partials[((size_t)blockIdx.x*128 + c)*2 + 0] = s;
            d_partials[((size_t)blockIdx.x*128 + c)*2 + 1] = q;
        }
    }
}

// ---------------- layer 3: bn2+relu on load, GEMM(128x64) --------------------
// tile: 128 out x 128 pos, 256 threads (tr=tid/16 in 0..15, tc=tid%16), 8x8 each
__global__ __launch_bounds__(256,2) void k_layer3(const float* __restrict__ W3) {
    extern __shared__ float sm[];
    float (*sg)[128] = (float(*)[128])sm;              // 64 x 128
    float (*sw)[128] = (float(*)[128])(sm + 64*128);   // 64 x 128
    int tid = threadIdx.x;
    int pos0 = blockIdx.x * 128;
    int wid = tid >> 5, lane = tid & 31;

    for (int i = tid; i < 128*64; i += 256) { int o = i/64, c = i%64; sw[c][o] = W3[i]; }
    for (int c = wid; c < 64; c += 8) {
        float a = d_ab[c*2], bp = d_ab[c*2+1];
        const float4* src = (const float4*)(d_h2 + (size_t)c*P_TOTAL + pos0);
        float4 v = src[lane];
        v.x=fmaxf(0.f,a*v.x+bp); v.y=fmaxf(0.f,a*v.y+bp);
        v.z=fmaxf(0.f,a*v.z+bp); v.w=fmaxf(0.f,a*v.w+bp);
        *(float4*)&sg[c][lane*4] = v;
    }
    __syncthreads();

    int tr = tid >> 4, tc = tid & 15;
    float acc[8][8];
#pragma unroll
    for (int i=0;i<8;i++)
#pragma unroll
        for (int j=0;j<8;j++) acc[i][j]=0.f;
#pragma unroll 2
    for (int k = 0; k < 64; k++) {
        float w[8], g[8];
        *(float4*)&w[0] = *(const float4*)&sw[k][tr*8];
        *(float4*)&w[4] = *(const float4*)&sw[k][tr*8+4];
        *(float4*)&g[0] = *(const float4*)&sg[k][tc*8];
        *(float4*)&g[4] = *(const float4*)&sg[k][tc*8+4];
#pragma unroll
        for (int i=0;i<8;i++)
#pragma unroll
            for (int j=0;j<8;j++) acc[i][j] += w[i]*g[j];
    }
#pragma unroll
    for (int i = 0; i < 8; i++) {
        int c = tr*8 + i;
        float* hp = d_h3 + (size_t)c*P_TOTAL + pos0 + tc*8;
        *(float4*)hp     = make_float4(acc[i][0],acc[i][1],acc[i][2],acc[i][3]);
        *(float4*)(hp+4) = make_float4(acc[i][4],acc[i][5],acc[i][6],acc[i][7]);
    }
#pragma unroll
    for (int i = 0; i < 8; i++) {
        float s = 0.f, q = 0.f;
#pragma unroll
        for (int j = 0; j < 8; j++) { s += acc[i][j]; q += acc[i][j]*acc[i][j]; }
#pragma unroll
        for (int o = 8; o > 0; o >>= 1) {   // reduce within 16-lane half
            s += __shfl_xor_sync(0xffffffffu, s, o);
            q += __shfl_xor_sync(0xffffffffu, q, o);
        }
        if (tc == 0) {
            int c = tr*8 + i;
            d_partials[((size_t)blockIdx.x*128 + c)*2 + 0] = s;
            d_partials[((size_t)blockIdx.x*128 + c)*2 + 1] = q;
        }
    }
}

// ---------------- bn3 + relu + max over nsample ------------------------------
__global__ void k_maxpool(float* __restrict__ feats) {
    int gid = blockIdx.x*blockDim.x + threadIdx.x;   // b*128*2048 + o*2048 + s
    if (gid >= BB*128*NPOINT) return;
    int s = gid & 2047;
    int o = (gid >> 11) & 127;
    int b = gid >> 18;
    float a = d_ab[o*2], bp = d_ab[o*2+1];
    const float4* hp = (const float4*)(d_h3 + (size_t)o*P_TOTAL
                                       + ((size_t)(b*NPOINT + s))*NSAMPLE);
    float m = 0.0f;   // relu lower bound
#pragma unroll
    for (int i = 0; i < 8; i++) {
        float4 v = hp[i];
        m = fmaxf(m, a*v.x+bp); m = fmaxf(m, a*v.y+bp);
        m = fmaxf(m, a*v.z+bp); m = fmaxf(m, a*v.w+bp);
    }
    feats[gid] = m;
}

// ---------------- launch ------------------------------------------------------
extern "C" void kernel_launch(void* const* d_in, const int* in_sizes, int n_in,
                              void* d_out, int out_size) {
    const float* xyz      = (const float*)d_in[0];
    const float* features = (const float*)d_in[1];
    const float* W1 = (const float*)d_in[2];
    const float* g1 = (const float*)d_in[3];
    const float* b1 = (const float*)d_in[4];
    const float* W2 = (const float*)d_in[5];
    const float* g2 = (const float*)d_in[6];
    const float* b2 = (const float*)d_in[7];
    const float* W3 = (const float*)d_in[8];
    const float* g3 = (const float*)d_in[9];
    const float* b3 = (const float*)d_in[10];
    float* out    = (float*)d_out;
    float* newxyz = out;                       // 8*2048*3
    float* feats  = out + BB*NPOINT*3;         // 8*128*2048

    const int SM1 = (67*256 + 67*64) * 4;      // 85760
    const int SM2 = (64*256 + 64*64) * 4;      // 81920
    const int SM3 = (64*128 + 64*128) * 4;     // 65536
    cudaFuncSetAttribute(k_layer1, cudaFuncAttributeMaxDynamicSharedMemorySize, SM1);
    cudaFuncSetAttribute(k_layer2, cudaFuncAttributeMaxDynamicSharedMemorySize, SM2);
    cudaFuncSetAttribute(k_layer3, cudaFuncAttributeMaxDynamicSharedMemorySize, SM3);

    k_transpose<<<dim3(NN/32, CC/32, BB), dim3(32,8)>>>(features);
    k_fps<<<BB, 512>>>(xyz, newxyz);
    k_ballquery<<<(BB*NPOINT)/4, 128>>>(xyz, newxyz);

    k_layer1<<<P_TOTAL/256, 256, SM1>>>(xyz, newxyz, W1);
    k_stats<<<64, 256>>>(g1, b1, P_TOTAL/256);
    k_layer2<<<P_TOTAL/256, 256, SM2>>>(W2);
    k_stats<<<64, 256>>>(g2, b2, P_TOTAL/256);
    k_layer3<<<P_TOTAL/128, 256, SM3>>>(W3);
    k_stats<<<128, 256>>>(g3, b3, P_TOTAL/128);
    k_maxpool<<<(BB*128*NPOINT)/256, 256>>>(feats);
}